// round 2
// baseline (speedup 1.0000x reference)
#include <cuda_runtime.h>
#include <math.h>
#include <float.h>

#define NB 8
#define NT 2048
#define NC 2048
#define NE 32
#define NH 64
#define HC (NH*NC)
#define NROWS (NB*NT)

typedef unsigned long long ull;

// ---------------- scratch (device globals: no allocation allowed) ----------------
__device__ __align__(16) float g_part[NB*16*NC];     // per-(b, t-chunk) column sums
__device__ __align__(16) float g_seq[NB*NC];         // per-b column sums (unnormalized mean)
__device__ float g_dots[NE + NB + NB*NE];            // sim col norms^2, seq norms^2, dots
__device__ float g_rout[NB*NE];                      // routing weights
__device__ __align__(16) float g_wv[NB*HC];          // routing-folded W_v  (b,h,c)
__device__ __align__(16) float g_wo[NB*HC];          // routing-folded W_o  (b,h,c)
__device__ __align__(16) float g_comb2[2*NROWS*NH];  // GEMM1 k-split partials
__device__ __align__(16) float g_comb[NROWS*NH];     // summed (b,t,h)

// ---------------- packed fp32x2 helpers (SASS FFMA2, exact fp32) ----------------
__device__ __forceinline__ void fma2(ull& d, ull a, ull b){
    asm("fma.rn.f32x2 %0, %1, %2, %0;" : "+l"(d) : "l"(a), "l"(b));
}
__device__ __forceinline__ ull pk2(float lo, float hi){
    ull r; asm("mov.b64 %0, {%1, %2};" : "=l"(r) : "f"(lo), "f"(hi)); return r;
}
__device__ __forceinline__ float2 upk2(ull v){
    float2 f; asm("mov.b64 {%0, %1}, %2;" : "=f"(f.x), "=f"(f.y) : "l"(v)); return f;
}
__device__ __forceinline__ float fcomp(const float4& v, int i){
    return i==0 ? v.x : (i==1 ? v.y : (i==2 ? v.z : v.w));
}
// XOR swizzles: conflict-free transpose-writes AND strided reads, zero padding.
__device__ __forceinline__ int swzA(int kf4, int m){ return m ^ ((kf4 ^ (m>>3)) & 7); }
__device__ __forceinline__ int swzB(int kf4, int n){ return n ^ (kf4 & 7); }

#define CP_ASYNC16(dst,src) asm volatile("cp.async.cg.shared.global [%0], [%1], 16;" :: "r"(dst), "l"(src))
#define CP_COMMIT() asm volatile("cp.async.commit_group;")
#define CP_WAIT(n)  asm volatile("cp.async.wait_group %0;" :: "n"(n))

__device__ __forceinline__ float wredsum(float v){
    #pragma unroll
    for (int o=16;o>0;o>>=1) v += __shfl_xor_sync(0xffffffffu, v, o);
    return v;
}
__device__ __forceinline__ float wredmax(float v){
    #pragma unroll
    for (int o=16;o>0;o>>=1) v = fmaxf(v, __shfl_xor_sync(0xffffffffu, v, o));
    return v;
}

// ---------------- 1) partial column sums over T (routing mean) ----------------
__global__ void k_mean(const float* __restrict__ X){
    int c = blockIdx.x*256 + threadIdx.x;
    int s = blockIdx.y, b = blockIdx.z;
    const float* p = X + ((size_t)b*NT + (size_t)s*128)*NC + c;
    float a0=0.f,a1=0.f,a2=0.f,a3=0.f;
    for (int t=0;t<128;t+=4){
        a0 += p[0]; a1 += p[NC]; a2 += p[2*NC]; a3 += p[3*NC];
        p += (size_t)4*NC;
    }
    g_part[(b*16+s)*NC + c] = (a0+a1)+(a2+a3);
}

__global__ void k_seqsum(){
    int idx = blockIdx.x*256 + threadIdx.x;   // over NB*NC
    int b = idx / NC, c = idx % NC;
    float v = 0.f;
    #pragma unroll
    for (int s=0;s<16;s++) v += g_part[(b*16+s)*NC + c];
    g_seq[idx] = v;
}

// ---------------- 2) norms + affinity dots ----------------
__global__ void k_dots(const float* __restrict__ sim){
    __shared__ float sred[4];
    int task = blockIdx.x;
    int tid = threadIdx.x; // 128 threads
    float acc = 0.f;
    if (task < NE){
        int e = task;
        for (int c = tid; c < NC; c += 128){ float v = sim[c*NE + e]; acc += v*v; }
    } else if (task < NE+NB){
        int b = task - NE;
        for (int c = tid; c < NC; c += 128){ float v = g_seq[b*NC + c]; acc += v*v; }
    } else {
        int p = task - NE - NB;
        int b = p >> 5, e = p & 31;
        for (int c = tid; c < NC; c += 128){ acc += g_seq[b*NC + c] * sim[c*NE + e]; }
    }
    acc = wredsum(acc);
    if ((tid & 31) == 0) sred[tid>>5] = acc;
    __syncthreads();
    if (tid == 0) g_dots[task] = (sred[0]+sred[1])+(sred[2]+sred[3]);
}

// ---------------- 3) gating: mask, fallback top-16, softmax ----------------
__global__ void k_gatefin(const float* __restrict__ gates){
    int tid = threadIdx.x;        // 256 threads: warp = batch, lane = expert
    int lane = tid & 31, b = tid >> 5;
    float nsim2 = g_dots[lane];
    float nseq2 = g_dots[NE + b];
    float dot   = g_dots[NE + NB + b*NE + lane];
    float aff = dot / sqrtf(nsim2 * nseq2);        // cosine (scale-invariant)
    float sig = 1.f / (1.f + expf(-gates[lane]));
    float logit = aff - sig;
    float gated = fmaxf(logit, 0.f);
    bool  act = gated > 0.f;
    unsigned actm = __ballot_sync(0xffffffffu, act);
    bool use = act;
    if (actm == 0u){
        // fallback: top-(E/2)=16 of logits, jax tie-break = lower index first
        int rank = 0;
        #pragma unroll
        for (int e=0;e<NE;e++){
            float le = __shfl_sync(0xffffffffu, logit, e);
            rank += (le > logit) || (le == logit && e < lane);
        }
        use = rank < 16;
    }
    float v = use ? gated : -FLT_MAX;
    float mx = wredmax(v);
    float ex = use ? expf(gated - mx) : 0.f;
    float sm = wredsum(ex);
    g_rout[tid] = ex / sm;
}

// ---------------- 4) fold routing into effective W_v / W_o ----------------
__global__ void k_weff(const float* __restrict__ w_v, const float* __restrict__ o_w){
    __shared__ float r[NB*NE];
    int tid = threadIdx.x;
    r[tid] = g_rout[tid];
    __syncthreads();
    int j = blockIdx.x*256 + tid;   // over HC
    float accv[NB], acco[NB];
    #pragma unroll
    for (int b=0;b<NB;b++){ accv[b]=0.f; acco[b]=0.f; }
    for (int e=0;e<NE;e++){
        float wv = w_v[(size_t)e*HC + j];
        float wo = o_w[(size_t)e*HC + j];
        #pragma unroll
        for (int b=0;b<NB;b++){
            float rr = r[b*NE+e];
            accv[b] = fmaf(rr, wv, accv[b]);
            acco[b] = fmaf(rr, wo, acco[b]);
        }
    }
    #pragma unroll
    for (int b=0;b<NB;b++){
        g_wv[(size_t)b*HC + j] = accv[b];
        g_wo[(size_t)b*HC + j] = acco[b];
    }
}

// ---------------- 5) GEMM1: comb_part[ks] = X(:,kslice) @ Wv_eff(:,kslice)^T ----------------
// tile M=128(t) x N=64(h) x K=32, 128 threads, 8x8 per thread, cp.async double buffer
__global__ void __launch_bounds__(128) k_gemm1(const float* __restrict__ X){
    __shared__ float4 As[2][8][128];   // [buf][kf4][m swizzled], f4 = 4 k-values
    __shared__ float4 Bs[2][8][64];    // [buf][kf4][h swizzled]
    int tid = threadIdx.x;
    int mt = blockIdx.x, ks = blockIdx.y, b = blockIdx.z;
    int t0 = mt*128;
    const float* Ag = X    + ((size_t)(b*NT + t0))*NC + (size_t)ks*1024;
    const float* Bg = g_wv + (size_t)b*HC              + (size_t)ks*1024;
    int mi = tid & 15, ni = tid >> 4;
    int m0 = mi*8, n0 = ni*8;

    ull acc[8][4];
    #pragma unroll
    for (int j=0;j<8;j++){
        #pragma unroll
        for (int p=0;p<4;p++) acc[j][p] = 0ull;
    }

    // prologue load tile 0
    {
        #pragma unroll
        for (int i=0;i<8;i++){
            int f4 = tid + i*128; int m = f4>>3, kf4 = f4&7;
            unsigned d = (unsigned)__cvta_generic_to_shared(&As[0][kf4][swzA(kf4,m)]);
            CP_ASYNC16(d, Ag + (size_t)m*NC + kf4*4);
        }
        #pragma unroll
        for (int i=0;i<4;i++){
            int f4 = tid + i*128; int h = f4>>3, kf4 = f4&7;
            unsigned d = (unsigned)__cvta_generic_to_shared(&Bs[0][kf4][swzB(kf4,h)]);
            CP_ASYNC16(d, Bg + (size_t)h*NC + kf4*4);
        }
        CP_COMMIT();
    }

    for (int t=0;t<32;t++){
        int buf = t & 1;
        if (t+1 < 32){
            int kb = (t+1)*32, nb = buf^1;
            #pragma unroll
            for (int i=0;i<8;i++){
                int f4 = tid + i*128; int m = f4>>3, kf4 = f4&7;
                unsigned d = (unsigned)__cvta_generic_to_shared(&As[nb][kf4][swzA(kf4,m)]);
                CP_ASYNC16(d, Ag + (size_t)m*NC + kb + kf4*4);
            }
            #pragma unroll
            for (int i=0;i<4;i++){
                int f4 = tid + i*128; int h = f4>>3, kf4 = f4&7;
                unsigned d = (unsigned)__cvta_generic_to_shared(&Bs[nb][kf4][swzB(kf4,h)]);
                CP_ASYNC16(d, Bg + (size_t)h*NC + kb + kf4*4);
            }
            CP_COMMIT();
            CP_WAIT(1);
        } else {
            CP_WAIT(0);
        }
        __syncthreads();
        #pragma unroll
        for (int kk=0;kk<8;kk++){
            float4 a4[8], b4[8];
            #pragma unroll
            for (int j=0;j<8;j++) a4[j] = As[buf][kk][swzA(kk, m0+j)];
            #pragma unroll
            for (int j=0;j<8;j++) b4[j] = Bs[buf][kk][swzB(kk, n0+j)];
            #pragma unroll
            for (int dk=0;dk<4;dk++){
                ull bb[4];
                #pragma unroll
                for (int p=0;p<4;p++) bb[p] = pk2(fcomp(b4[2*p],dk), fcomp(b4[2*p+1],dk));
                #pragma unroll
                for (int j=0;j<8;j++){
                    float a = fcomp(a4[j],dk);
                    ull aa = pk2(a,a);
                    fma2(acc[j][0], aa, bb[0]);
                    fma2(acc[j][1], aa, bb[1]);
                    fma2(acc[j][2], aa, bb[2]);
                    fma2(acc[j][3], aa, bb[3]);
                }
            }
        }
        __syncthreads();
    }

    float* outp = g_comb2 + (size_t)ks*NROWS*NH;
    #pragma unroll
    for (int j=0;j<8;j++){
        float2 c0 = upk2(acc[j][0]), c1 = upk2(acc[j][1]);
        float2 c2 = upk2(acc[j][2]), c3 = upk2(acc[j][3]);
        float4 o0 = make_float4(c0.x,c0.y,c1.x,c1.y);
        float4 o1 = make_float4(c2.x,c2.y,c3.x,c3.y);
        size_t r = (size_t)(b*NT + t0 + m0 + j)*NH + n0;
        *(float4*)(outp + r)     = o0;
        *(float4*)(outp + r + 4) = o1;
    }
}

// ---------------- 6) sum k-split partials ----------------
__global__ void k_addcomb(){
    int i = blockIdx.x*256 + threadIdx.x;  // over NROWS*NH/4 float4s
    const float4* p0 = (const float4*)g_comb2;
    const float4* p1 = (const float4*)(g_comb2 + (size_t)NROWS*NH);
    float4 a = p0[i], b = p1[i];
    float4 o = make_float4(a.x+b.x, a.y+b.y, a.z+b.z, a.w+b.w);
    ((float4*)g_comb)[i] = o;
}

// ---------------- 7) GEMM2: out = comb @ Wo_eff  (K=64) ----------------
// tile M=128 x N=64 x K=64 (single shot), 128 threads, 8x8 per thread
__global__ void __launch_bounds__(128) k_gemm2(float* __restrict__ out){
    __shared__ float4 As[16][128];   // [kf4][m swizzled]
    __shared__ float  Bs[64][64];    // natural [k][n] (reads broadcast, no conflicts)
    int tid = threadIdx.x;
    int nt = blockIdx.x, mt = blockIdx.y;
    int mbase = mt*128;              // global row over NB*NT (no batch straddle)
    int b = mbase / NT;
    int d0 = nt*64;
    const float* Ag = g_comb + (size_t)mbase*NH;
    const float* Bg = g_wo   + (size_t)b*HC + d0;
    int mi = tid & 15, ni = tid >> 4;
    int m0 = mi*8, n0 = ni*8;

    #pragma unroll
    for (int i=0;i<16;i++){
        int f4 = tid + i*128; int m = f4>>4, kf4 = f4&15;
        As[kf4][swzA(kf4,m)] = *(const float4*)(Ag + (size_t)m*NH + kf4*4);
    }
    #pragma unroll
    for (int i=0;i<8;i++){
        int f4 = tid + i*128; int h = f4>>4, c4 = f4&15;
        *(float4*)&Bs[h][c4*4] = *(const float4*)(Bg + (size_t)h*NC + c4*4);
    }
    __syncthreads();

    ull acc[8][4];
    #pragma unroll
    for (int j=0;j<8;j++){
        #pragma unroll
        for (int p=0;p<4;p++) acc[j][p] = 0ull;
    }

    #pragma unroll 4
    for (int kk=0;kk<16;kk++){
        float4 a4[8];
        #pragma unroll
        for (int j=0;j<8;j++) a4[j] = As[kk][swzA(kk, m0+j)];
        #pragma unroll
        for (int dk=0;dk<4;dk++){
            int k = kk*4 + dk;
            float4 b0 = *(const float4*)&Bs[k][n0];
            float4 b1 = *(const float4*)&Bs[k][n0+4];
            ull bb0 = pk2(b0.x,b0.y), bb1 = pk2(b0.z,b0.w);
            ull bb2 = pk2(b1.x,b1.y), bb3 = pk2(b1.z,b1.w);
            #pragma unroll
            for (int j=0;j<8;j++){
                float a = fcomp(a4[j],dk);
                ull aa = pk2(a,a);
                fma2(acc[j][0], aa, bb0);
                fma2(acc[j][1], aa, bb1);
                fma2(acc[j][2], aa, bb2);
                fma2(acc[j][3], aa, bb3);
            }
        }
    }

    #pragma unroll
    for (int j=0;j<8;j++){
        float2 c0 = upk2(acc[j][0]), c1 = upk2(acc[j][1]);
        float2 c2 = upk2(acc[j][2]), c3 = upk2(acc[j][3]);
        float4 o0 = make_float4(c0.x,c0.y,c1.x,c1.y);
        float4 o1 = make_float4(c2.x,c2.y,c3.x,c3.y);
        size_t r = (size_t)(mbase + m0 + j)*NC + d0 + n0;
        *(float4*)(out + r)     = o0;
        *(float4*)(out + r + 4) = o1;
    }
}

// ---------------- launch ----------------
extern "C" void kernel_launch(void* const* d_in, const int* in_sizes, int n_in,
                              void* d_out, int out_size){
    const float* X     = (const float*)d_in[0];
    const float* sim   = (const float*)d_in[1];
    const float* gates = (const float*)d_in[2];
    const float* w_v   = (const float*)d_in[5];
    const float* o_w   = (const float*)d_in[6];
    float* out = (float*)d_out;

    k_mean  <<<dim3(NC/256, 16, NB), 256>>>(X);
    k_seqsum<<<NB*NC/256, 256>>>();
    k_dots  <<<NE + NB + NB*NE, 128>>>(sim);
    k_gatefin<<<1, NB*NE>>>(gates);
    k_weff  <<<HC/256, 256>>>(w_v, o_w);
    k_gemm1 <<<dim3(NT/128, 2, NB), 128>>>(X);
    k_addcomb<<<NROWS*NH/4/256, 256>>>();
    k_gemm2 <<<dim3(NC/64, NROWS/128), 128>>>(out);
    (void)in_sizes; (void)n_in; (void)out_size;
}

// round 3
// speedup vs baseline: 1.1051x; 1.1051x over previous
#include <cuda_runtime.h>
#include <math.h>
#include <float.h>

#define NB 8
#define NT 2048
#define NC 2048
#define NE 32
#define NH 64
#define HC (NH*NC)
#define NROWS (NB*NT)
#define KSPLIT 4

typedef unsigned long long ull;

// ---------------- scratch ----------------
__device__ __align__(16) float g_part[NB*16*NC];        // per-(b, t-chunk) column sums
__device__ float g_dots[NE + NB + NB*NE];               // norms^2 + dots
__device__ __align__(16) float g_wv[NB*HC];             // routing-folded W_v (b,h,c)
__device__ __align__(16) float g_wo[NB*HC];             // routing-folded W_o (b,h,c)
__device__ __align__(16) float g_comb2[KSPLIT*NROWS*NH];
__device__ __align__(16) float g_comb[NROWS*NH];

// ---------------- helpers ----------------
__device__ __forceinline__ void fma2(ull& d, ull a, ull b){
    asm("fma.rn.f32x2 %0, %1, %2, %0;" : "+l"(d) : "l"(a), "l"(b));
}
__device__ __forceinline__ ull pk2(float lo, float hi){
    ull r; asm("mov.b64 %0, {%1, %2};" : "=l"(r) : "f"(lo), "f"(hi)); return r;
}
__device__ __forceinline__ float2 upk2(ull v){
    float2 f; asm("mov.b64 {%0, %1}, %2;" : "=f"(f.x), "=f"(f.y) : "l"(v)); return f;
}
__device__ __forceinline__ float fcomp(const float4& v, int i){
    return i==0 ? v.x : (i==1 ? v.y : (i==2 ? v.z : v.w));
}
__device__ __forceinline__ int swzA(int k, int m){ return m ^ ((k ^ (m>>3)) & 7); }

#define CP_ASYNC16(dst,src) asm volatile("cp.async.cg.shared.global [%0], [%1], 16;" :: "r"(dst), "l"(src))
#define CP_COMMIT() asm volatile("cp.async.commit_group;")
#define CP_WAIT0()  asm volatile("cp.async.wait_group 0;")

__device__ __forceinline__ float wredsum(float v){
    #pragma unroll
    for (int o=16;o>0;o>>=1) v += __shfl_xor_sync(0xffffffffu, v, o);
    return v;
}
__device__ __forceinline__ float wredmax(float v){
    #pragma unroll
    for (int o=16;o>0;o>>=1) v = fmaxf(v, __shfl_xor_sync(0xffffffffu, v, o));
    return v;
}

// ---------------- 1) partial column sums over T ----------------
__global__ void k_mean(const float* __restrict__ X){
    int c = blockIdx.x*256 + threadIdx.x;
    int s = blockIdx.y, b = blockIdx.z;
    const float* p = X + ((size_t)b*NT + (size_t)s*128)*NC + c;
    float a0=0.f,a1=0.f,a2=0.f,a3=0.f;
    for (int t=0;t<128;t+=4){
        a0 += p[0]; a1 += p[NC]; a2 += p[2*NC]; a3 += p[3*NC];
        p += (size_t)4*NC;
    }
    g_part[(b*16+s)*NC + c] = (a0+a1)+(a2+a3);
}

// ---------------- 2) norms + affinity dots (g_part summed inline) ----------------
__global__ void k_dots(const float* __restrict__ sim){
    __shared__ float sred[4];
    int task = blockIdx.x;
    int tid = threadIdx.x; // 128 threads
    float acc = 0.f;
    if (task < NE){
        int e = task;
        for (int c = tid; c < NC; c += 128){ float v = sim[c*NE + e]; acc += v*v; }
    } else if (task < NE+NB){
        int b = task - NE;
        for (int c = tid; c < NC; c += 128){
            float v = 0.f;
            #pragma unroll
            for (int s=0;s<16;s++) v += g_part[(b*16+s)*NC + c];
            acc += v*v;
        }
    } else {
        int p = task - NE - NB;
        int b = p >> 5, e = p & 31;
        for (int c = tid; c < NC; c += 128){
            float v = 0.f;
            #pragma unroll
            for (int s=0;s<16;s++) v += g_part[(b*16+s)*NC + c];
            acc += v * sim[c*NE + e];
        }
    }
    acc = wredsum(acc);
    if ((tid & 31) == 0) sred[tid>>5] = acc;
    __syncthreads();
    if (tid == 0) g_dots[task] = (sred[0]+sred[1])+(sred[2]+sred[3]);
}

// ---------------- 3) gating (recomputed per block) + fold into W_v/W_o ----------------
__global__ void k_weff(const float* __restrict__ gates,
                       const float* __restrict__ w_v, const float* __restrict__ o_w){
    __shared__ float r[NB*NE];
    int tid = threadIdx.x;   // 256 threads: warp = batch, lane = expert
    {
        int lane = tid & 31, b = tid >> 5;
        float nsim2 = g_dots[lane];
        float nseq2 = g_dots[NE + b];
        float dot   = g_dots[NE + NB + b*NE + lane];
        float aff = dot / sqrtf(nsim2 * nseq2);
        float sig = 1.f / (1.f + expf(-gates[lane]));
        float logit = aff - sig;
        float gated = fmaxf(logit, 0.f);
        bool  act = gated > 0.f;
        unsigned actm = __ballot_sync(0xffffffffu, act);
        bool use = act;
        if (actm == 0u){
            int rank = 0;
            #pragma unroll
            for (int e=0;e<NE;e++){
                float le = __shfl_sync(0xffffffffu, logit, e);
                rank += (le > logit) || (le == logit && e < lane);
            }
            use = rank < 16;
        }
        float v = use ? gated : -FLT_MAX;
        float mx = wredmax(v);
        float ex = use ? expf(gated - mx) : 0.f;
        float sm = wredsum(ex);
        r[tid] = ex / sm;
    }
    __syncthreads();
    int j = blockIdx.x*256 + tid;   // over HC
    float accv[NB], acco[NB];
    #pragma unroll
    for (int b=0;b<NB;b++){ accv[b]=0.f; acco[b]=0.f; }
    for (int e=0;e<NE;e++){
        float wv = w_v[(size_t)e*HC + j];
        float wo = o_w[(size_t)e*HC + j];
        #pragma unroll
        for (int b=0;b<NB;b++){
            float rr = r[b*NE+e];
            accv[b] = fmaf(rr, wv, accv[b]);
            acco[b] = fmaf(rr, wo, acco[b]);
        }
    }
    #pragma unroll
    for (int b=0;b<NB;b++){
        g_wv[(size_t)b*HC + j] = accv[b];
        g_wo[(size_t)b*HC + j] = acco[b];
    }
}

// ---------------- 4) GEMM1: g_comb2[ks] = X(:,kslice) @ Wv_eff(:,kslice)^T ----------------
// block tile 256(m) x 64(n), K=16 double-buffered stages, 128 threads, 8x16/thread
__global__ void __launch_bounds__(128, 2) k_gemm1(const float* __restrict__ X){
    __shared__ __align__(16) float4 As[2][4][256];  // [buf][kf4][m swz]  32KB
    __shared__ __align__(16) float  Bst[2][16][64]; // [buf][k][n]         8KB
    int tid = threadIdx.x;
    int mt = blockIdx.x, ks = blockIdx.y, b = blockIdx.z;
    const float* Ag = X    + ((size_t)(b*NT + mt*256))*NC + ks*512;
    const float* Bg = g_wv + (size_t)b*HC                 + ks*512;
    int mi = tid & 31, ni = tid >> 5;
    int m0 = mi*8, n0 = ni*16;
    // A cp.async mapping: f = tid + i*128 -> m = f>>2, kf4 = f&3 (8 tasks)
    int am[8], akf4[8];
    #pragma unroll
    for (int i=0;i<8;i++){ int f = tid + i*128; am[i]=f>>2; akf4[i]=f&3; }
    // B LDG mapping: bkf4 = tid&3, n = (tid>>2) + 32*i (2 tasks)
    int bkf4 = tid & 3, bn = tid >> 2;

    ull acc[8][8];
    #pragma unroll
    for (int j=0;j<8;j++){
        #pragma unroll
        for (int p=0;p<8;p++) acc[j][p] = 0ull;
    }

    // prologue: stage 0
    #pragma unroll
    for (int i=0;i<8;i++){
        unsigned d = (unsigned)__cvta_generic_to_shared(&As[0][akf4[i]][swzA(akf4[i], am[i])]);
        CP_ASYNC16(d, Ag + (size_t)am[i]*NC + akf4[i]*4);
    }
    CP_COMMIT();
    float4 bpre[2];
    #pragma unroll
    for (int i=0;i<2;i++) bpre[i] = *(const float4*)(Bg + (size_t)(bn + 32*i)*NC + bkf4*4);
    CP_WAIT0();
    #pragma unroll
    for (int i=0;i<2;i++){
        #pragma unroll
        for (int j2=0;j2<4;j2++) Bst[0][bkf4*4 + j2][bn + 32*i] = fcomp(bpre[i], j2);
    }
    __syncthreads();

    for (int t=0;t<32;t++){
        int buf = t & 1;
        if (t+1 < 32){
            int kb = (t+1)*16, nb = buf^1;
            #pragma unroll
            for (int i=0;i<8;i++){
                unsigned d = (unsigned)__cvta_generic_to_shared(&As[nb][akf4[i]][swzA(akf4[i], am[i])]);
                CP_ASYNC16(d, Ag + (size_t)am[i]*NC + kb + akf4[i]*4);
            }
            CP_COMMIT();
            #pragma unroll
            for (int i=0;i<2;i++) bpre[i] = *(const float4*)(Bg + (size_t)(bn + 32*i)*NC + kb + bkf4*4);
        }
        // compute K=16
        #pragma unroll
        for (int kk=0;kk<4;kk++){
            float4 a4[8];
            #pragma unroll
            for (int j=0;j<8;j++) a4[j] = As[buf][kk][swzA(kk, m0+j)];
            #pragma unroll
            for (int dk=0;dk<4;dk++){
                const ulonglong2* br = (const ulonglong2*)&Bst[buf][kk*4+dk][n0];
                ulonglong2 q0=br[0], q1=br[1], q2=br[2], q3=br[3];
                #pragma unroll
                for (int j=0;j<8;j++){
                    float a = fcomp(a4[j], dk);
                    ull aa = pk2(a, a);
                    fma2(acc[j][0], aa, q0.x); fma2(acc[j][1], aa, q0.y);
                    fma2(acc[j][2], aa, q1.x); fma2(acc[j][3], aa, q1.y);
                    fma2(acc[j][4], aa, q2.x); fma2(acc[j][5], aa, q2.y);
                    fma2(acc[j][6], aa, q3.x); fma2(acc[j][7], aa, q3.y);
                }
            }
        }
        if (t+1 < 32){
            int nb = buf^1;
            #pragma unroll
            for (int i=0;i<2;i++){
                #pragma unroll
                for (int j2=0;j2<4;j2++) Bst[nb][bkf4*4 + j2][bn + 32*i] = fcomp(bpre[i], j2);
            }
            CP_WAIT0();
        }
        __syncthreads();
    }

    float* outp = g_comb2 + (size_t)ks*NROWS*NH;
    #pragma unroll
    for (int j=0;j<8;j++){
        size_t r = (size_t)(b*NT + mt*256 + m0 + j)*NH + n0;
        #pragma unroll
        for (int p=0;p<4;p++){
            float2 c0 = upk2(acc[j][2*p]), c1 = upk2(acc[j][2*p+1]);
            *(float4*)(outp + r + p*4) = make_float4(c0.x, c0.y, c1.x, c1.y);
        }
    }
}

// ---------------- 5) sum k-split partials ----------------
__global__ void k_addcomb(){
    int i = blockIdx.x*256 + threadIdx.x;
    const float4* p0 = (const float4*)g_comb2;
    const size_t st = (size_t)NROWS*NH/4;
    float4 a = p0[i], b = p0[i+st], c = p0[i+2*st], d = p0[i+3*st];
    float4 o = make_float4((a.x+b.x)+(c.x+d.x), (a.y+b.y)+(c.y+d.y),
                           (a.z+b.z)+(c.z+d.z), (a.w+b.w)+(c.w+d.w));
    ((float4*)g_comb)[i] = o;
}

// ---------------- 6) GEMM2: out = comb @ Wo_eff  (K=64) ----------------
// block tile 128(m) x 128(n), A one-shot (K=64), B double-buffered K=16, 8x16/thread
__global__ void __launch_bounds__(128, 2) k_gemm2(float* __restrict__ out){
    __shared__ __align__(16) float4 As2[16][128];    // [kf4][m swz]  32KB
    __shared__ __align__(16) float4 Bs2[2][16][32];  // [buf][k][n4]  16KB
    int tid = threadIdx.x;
    int nt = blockIdx.x, mt = blockIdx.y;
    int mbase = mt*128;
    int b = mbase / NT;
    int d0 = nt*128;
    const float* Ag = g_comb + (size_t)mbase*NH;
    const float* Bg = g_wo   + (size_t)b*HC + d0;
    int mi = tid & 15, ni = tid >> 4;
    int m0 = mi*8, n0f4 = ni*4;

    // prologue: A (full K=64) + B stage 0
    #pragma unroll
    for (int i=0;i<16;i++){
        int f = tid + i*128; int m = f>>4, kf4 = f&15;
        unsigned d = (unsigned)__cvta_generic_to_shared(&As2[kf4][swzA(kf4, m)]);
        CP_ASYNC16(d, Ag + (size_t)m*NH + kf4*4);
    }
    #pragma unroll
    for (int i=0;i<4;i++){
        int f = tid + i*128; int n4 = f&31, k = f>>5;
        unsigned d = (unsigned)__cvta_generic_to_shared(&Bs2[0][k][n4]);
        CP_ASYNC16(d, Bg + (size_t)k*NC + n4*4);
    }
    CP_COMMIT();

    ull acc[8][8];
    #pragma unroll
    for (int j=0;j<8;j++){
        #pragma unroll
        for (int p=0;p<8;p++) acc[j][p] = 0ull;
    }

    for (int s=0;s<4;s++){
        CP_WAIT0();
        __syncthreads();
        if (s+1 < 4){
            int kb = (s+1)*16, nb = (s+1)&1;
            #pragma unroll
            for (int i=0;i<4;i++){
                int f = tid + i*128; int n4 = f&31, k = f>>5;
                unsigned d = (unsigned)__cvta_generic_to_shared(&Bs2[nb][k][n4]);
                CP_ASYNC16(d, Bg + (size_t)(kb + k)*NC + n4*4);
            }
            CP_COMMIT();
        }
        int buf = s & 1;
        #pragma unroll
        for (int kk=0;kk<4;kk++){
            int kf4 = s*4 + kk;
            float4 a4[8];
            #pragma unroll
            for (int j=0;j<8;j++) a4[j] = As2[kf4][swzA(kf4, m0+j)];
            #pragma unroll
            for (int dk=0;dk<4;dk++){
                const ulonglong2* br = (const ulonglong2*)&Bs2[buf][kk*4+dk][n0f4];
                ulonglong2 q0=br[0], q1=br[1];
                ull b0=q0.x, b1=q0.y, b2=q1.x, b3=q1.y;
                const ulonglong2* br2 = br + 2;
                ulonglong2 q2=br2[0], q3=br2[1];
                ull b4=q2.x, b5=q2.y, b6=q3.x, b7=q3.y;
                #pragma unroll
                for (int j=0;j<8;j++){
                    float a = fcomp(a4[j], dk);
                    ull aa = pk2(a, a);
                    fma2(acc[j][0], aa, b0); fma2(acc[j][1], aa, b1);
                    fma2(acc[j][2], aa, b2); fma2(acc[j][3], aa, b3);
                    fma2(acc[j][4], aa, b4); fma2(acc[j][5], aa, b5);
                    fma2(acc[j][6], aa, b6); fma2(acc[j][7], aa, b7);
                }
            }
        }
        __syncthreads();
    }

    #pragma unroll
    for (int j=0;j<8;j++){
        size_t r = (size_t)(mbase + m0 + j)*NC + d0 + n0f4*4;
        #pragma unroll
        for (int p=0;p<4;p++){
            float2 c0 = upk2(acc[j][2*p]), c1 = upk2(acc[j][2*p+1]);
            *(float4*)(out + r + p*4) = make_float4(c0.x, c0.y, c1.x, c1.y);
        }
    }
}

// ---------------- launch ----------------
extern "C" void kernel_launch(void* const* d_in, const int* in_sizes, int n_in,
                              void* d_out, int out_size){
    const float* X     = (const float*)d_in[0];
    const float* sim   = (const float*)d_in[1];
    const float* gates = (const float*)d_in[2];
    const float* w_v   = (const float*)d_in[5];
    const float* o_w   = (const float*)d_in[6];
    float* out = (float*)d_out;

    k_mean   <<<dim3(NC/256, 16, NB), 256>>>(X);
    k_dots   <<<NE + NB + NB*NE, 128>>>(sim);
    k_weff   <<<HC/256, 256>>>(gates, w_v, o_w);
    k_gemm1  <<<dim3(NT/256, KSPLIT, NB), 128>>>(X);
    k_addcomb<<<NROWS*NH/4/256, 256>>>();
    k_gemm2  <<<dim3(NC/128, NROWS/128), 128>>>(out);
    (void)in_sizes; (void)n_in; (void)out_size;
}